// round 15
// baseline (speedup 1.0000x reference)
#include <cuda_runtime.h>
#include <cstdint>

#define FULLMASK 0xffffffffu

constexpr int N = 8192, D = 32, C = 16;
constexpr int NC1 = 40;                   // stored cols for layer GEMMs (34 real)
constexpr int KSPLIT = 8;
constexpr int BM = 128, BK = 64;
constexpr int TILES = (N / KSPLIT) / BK;  // 16
constexpr int PITCH = 68;                 // smem row pitch in fp32 elems
constexpr int ASTG = BM * PITCH;          // 8704 floats per A stage
constexpr int STAGES = 2;

// ---- scratch (static device arrays; zero-initialized, never allocated) ----
__device__ __align__(256) float g_MtH[NC1 * N];   // M^T tf32-hi; rows 34..39 stay 0
__device__ __align__(256) float g_MtL[NC1 * N];   // M^T tf32-lo
__device__ __align__(256) float g_Pp[KSPLIT * N * NC1];
__device__ __align__(256) float g_Po[KSPLIT * N * C];

__device__ __forceinline__ float wsum(float v) {
#pragma unroll
    for (int o = 16; o > 0; o >>= 1) v += __shfl_xor_sync(FULLMASK, v, o);
    return v;
}
__device__ __forceinline__ float artanh_c(float v) {
    v = fminf(fmaxf(v, -0.99999988f), 0.99999988f);
    return atanhf(v);
}
__device__ __forceinline__ uint32_t tf32_hi(float v) {
    uint32_t r;
    asm("cvt.rna.tf32.f32 %0, %1;" : "=r"(r) : "f"(v));
    return r;
}

// ---- staged transposed hi/lo stores: [col][8 rows] -------------------------
__device__ __forceinline__ void stage_hl(float (*tH)[8], float (*tL)[8],
                                         int col, int w, float v)
{
    uint32_t h = tf32_hi(v);
    tH[col][w] = __uint_as_float(h);
    tL[col][w] = __uint_as_float(tf32_hi(v - __uint_as_float(h)));
}
template <int NCOLS>
__device__ __forceinline__ void store_cols_t(float (*tH)[8], float (*tL)[8],
                                             int tid, int row0)
{
    __syncthreads();
    if (tid < NCOLS) {
        uint4* dH = reinterpret_cast<uint4*>(&g_MtH[(size_t)tid * N + row0]);
        uint4* dL = reinterpret_cast<uint4*>(&g_MtL[(size_t)tid * N + row0]);
        const uint4* sH = reinterpret_cast<const uint4*>(&tH[tid][0]);
        const uint4* sL = reinterpret_cast<const uint4*>(&tL[tid][0]);
        dH[0] = sH[0]; dH[1] = sH[1];
        dL[0] = sL[0]; dL[1] = sL[1];
    }
}

// ---- prep math: x (lane=dim) -> stage gamma*XW | gamma-1 | 1 ---------------
__device__ __forceinline__ void prep_math(const float (*Ws)[D + 1], float x,
                                          int lane, int w,
                                          float (*tH)[8], float (*tL)[8])
{
    float xn = sqrtf(fmaxf(wsum(x * x), 1e-30f));
    float mx = 0.f;
#pragma unroll
    for (int d = 0; d < D; ++d)
        mx = fmaf(__shfl_sync(FULLMASK, x, d), Ws[d][lane], mx);
    float mxn = sqrtf(fmaxf(wsum(mx * mx), 1e-30f));
    float xw = tanhf(mxn / xn * artanh_c(xn)) / mxn * mx;
    float gamma = 2.f / fmaxf(1.f - wsum(xw * xw), 1e-15f);

    stage_hl(tH, tL, lane, w, gamma * xw);
    if (lane == 0) stage_hl(tH, tL, 32, w, gamma - 1.f);
    if (lane == 1) stage_hl(tH, tL, 33, w, 1.f);
}

// ---- post math: split partials -> layer output x (lane=dim) ----------------
__device__ __forceinline__ float post_math(int row, int lane)
{
    float nom = 0.f, den = 0.f, alp = 0.f;
#pragma unroll
    for (int s = 0; s < KSPLIT; ++s) {
        const float* pr = g_Pp + ((size_t)s * N + row) * NC1;
        nom += pr[lane]; den += pr[32]; alp += pr[33];
    }
    den = (den >= 0.f) ? fmaxf(den, 1e-10f) : fminf(den, -1e-10f);

    float v = nom / den;
    float vn = sqrtf(fmaxf(wsum(v * v), 1e-30f));
    float am = tanhf(0.5f * artanh_c(vn)) * (v / vn);
    float amn = sqrtf(fmaxf(wsum(am * am), 1e-30f));
    float axw = tanhf(alp * artanh_c(amn)) * (am / amn);
    float axwn = sqrtf(fmaxf(wsum(axw * axw), 1e-30f));
    float r = fmaxf(artanh_c(axwn) * (axw / axwn), 0.f);
    float rn = sqrtf(fmaxf(wsum(r * r), 1e-30f));
    return tanhf(rn) * (r / rn);
}

// ============================ layer-1 prep ==================================
__global__ void prep_kernel(const float* __restrict__ X0,
                            const float* __restrict__ W)
{
    __shared__ float Ws[D][D + 1];
    __shared__ float tH[NC1][8], tL[NC1][8];
    const int tid = threadIdx.x;
    for (int i = tid; i < D * D; i += blockDim.x) Ws[i >> 5][i & 31] = W[i];
    __syncthreads();

    const int lane = tid & 31, w = tid >> 5;
    const int row0 = blockIdx.x * 8;
    prep_math(Ws, X0[(row0 + w) * D + lane], lane, w, tH, tL);
    store_cols_t<34>(tH, tL, tid, row0);
}

// ============================ fused post + prep (layer 2) ===================
__global__ void post_prep_kernel(const float* __restrict__ W)
{
    __shared__ float Ws[D][D + 1];
    __shared__ float tH[NC1][8], tL[NC1][8];
    const int tid = threadIdx.x;
    for (int i = tid; i < D * D; i += blockDim.x) Ws[i >> 5][i & 31] = W[i];
    __syncthreads();

    const int lane = tid & 31, w = tid >> 5;
    const int row0 = blockIdx.x * 8;
    float x = post_math(row0 + w, lane);
    prep_math(Ws, x, lane, w, tH, tL);
    store_cols_t<34>(tH, tL, tid, row0);
}

// ============================ fused post + logits ===========================
__global__ void post_logits_kernel(const float* __restrict__ Wl,
                                   const float* __restrict__ pks)
{
    __shared__ float bs[C][D], ws[C][D];
    __shared__ float an_s[C], lam_s[C], b2_s[C];
    __shared__ float tH[C][8], tL[C][8];
    const int tid = threadIdx.x;
    for (int i = tid; i < C * D; i += blockDim.x) {
        const int c = i >> 5, d = i & 31;
        bs[c][d] = pks[i];
        ws[c][d] = Wl[d * C + c];
    }
    __syncthreads();
    if (tid < C) {
        float s2 = 0.f, b2 = 0.f;
        for (int d = 0; d < D; ++d) { s2 += ws[tid][d] * ws[tid][d]; b2 += bs[tid][d] * bs[tid][d]; }
        an_s[tid] = fmaxf(sqrtf(s2), 1e-10f);
        b2_s[tid] = b2;
        lam_s[tid] = 2.f / fmaxf(1.f - b2, 1e-15f);
    }
    __syncthreads();

    const int lane = tid & 31, w = tid >> 5;
    const int row0 = blockIdx.x * 8;
    float x = post_math(row0 + w, lane);
    float y2 = wsum(x * x);

#pragma unroll 1
    for (int c = 0; c < C; ++c) {
        float bd = bs[c][lane];
        float bx = wsum(bd * x);
        float b2 = b2_s[c];
        float c1 = 1.f - 2.f * bx + y2;
        float c2 = 1.f - b2;
        float dd = fmaxf(1.f - 2.f * bx + b2 * y2, 1e-15f);
        float z = (c2 * x - c1 * bd) / dd;
        float za = wsum(z * ws[c][lane]);
        float zn = fmaxf(sqrtf(fmaxf(wsum(z * z), 1e-30f)), 1e-10f);
        float dist = asinhf(2.f * za / ((1.f - zn * zn) * an_s[c]));
        float lg = lam_s[c] * an_s[c] * dist;   // lane-uniform
        if (lane == 0) stage_hl(tH, tL, c, w, lg);
    }
    store_cols_t<C>(tH, tL, tid, row0);
}

// ============================ 3xTF32 MMA GEMM (cp.async) ====================
// P[split][r][c] = sum over k in split of A[r,k] * Mt[c][k]   (near-fp32)
// A fp32 streamed, split to tf32 hi/lo in registers; M pre-split in DRAM.
__device__ __forceinline__ void cpa16(uint32_t dst, const void* src) {
    asm volatile("cp.async.cg.shared.global [%0], [%1], 16;" :: "r"(dst), "l"(src));
}

template <int NT>
__global__ void __launch_bounds__(256, 2) gemm_mma(const float* __restrict__ A)
{
    constexpr int NR = NT * 8;                 // B rows (output cols)
    constexpr int BSTG = NR * PITCH;           // floats per B array per stage
    constexpr int STAGE_E = ASTG + 2 * BSTG;   // floats per stage
    constexpr int ACH = BM * (BK / 4);         // 16B chunks per A tile (2048)
    constexpr int BCH = NR * (BK / 4);         // 16B chunks per B array tile

    extern __shared__ float dyn[];
    const uint32_t sbase = (uint32_t)__cvta_generic_to_shared(dyn);

    const int tid = threadIdx.x, wid = tid >> 5, lane = tid & 31;
    const int row0 = blockIdx.x * BM;
    const size_t kb0 = (size_t)blockIdx.y * (N / KSPLIT);

    // tile loader: stage s gets tile t
    auto load_tile = [&](int t, int s) {
        const uint32_t sb = sbase + s * STAGE_E * 4;
        const size_t kofs = kb0 + (size_t)t * BK;
#pragma unroll
        for (int p = 0; p < ACH / 256; ++p) {       // 8 chunks per thread
            const int i = tid + 256 * p;
            const int row = i >> 4, c4 = i & 15;
            cpa16(sb + (row * PITCH + c4 * 4) * 4,
                  A + (size_t)(row0 + row) * N + kofs + c4 * 4);
        }
        for (int i = tid; i < BCH; i += 256) {
            const int row = i >> 4, c4 = i & 15;
            cpa16(sb + (ASTG + row * PITCH + c4 * 4) * 4,
                  g_MtH + (size_t)row * N + kofs + c4 * 4);
            cpa16(sb + (ASTG + BSTG + row * PITCH + c4 * 4) * 4,
                  g_MtL + (size_t)row * N + kofs + c4 * 4);
        }
        asm volatile("cp.async.commit_group;" ::: "memory");
    };

    float acc[NT][4];
#pragma unroll
    for (int j = 0; j < NT; ++j)
#pragma unroll
        for (int q = 0; q < 4; ++q) acc[j][q] = 0.f;

    load_tile(0, 0);
    load_tile(1, 1);

    const int arow = wid * 16 + (lane >> 2);   // a0/a2 row
    const int kq = lane & 3;

    for (int t = 0; t < TILES; ++t) {
        asm volatile("cp.async.wait_group 1;" ::: "memory");  // tile t resident
        __syncthreads();

        const float* aS = dyn + (t & 1) * STAGE_E;
        const float* bH = aS + ASTG;
        const float* bL = bH + BSTG;

#pragma unroll
        for (int s = 0; s < 4; ++s) {   // 2 k8-steps per s (k = s*16 .. s*16+15)
#pragma unroll
            for (int h = 0; h < 2; ++h) {
                const int kc = s * 16 + h * 8 + kq;
                float a0 = aS[arow * PITCH + kc];
                float a1 = aS[(arow + 8) * PITCH + kc];
                float a2 = aS[arow * PITCH + kc + 4];
                float a3 = aS[(arow + 8) * PITCH + kc + 4];
                uint32_t ah0 = tf32_hi(a0), ah1 = tf32_hi(a1);
                uint32_t ah2 = tf32_hi(a2), ah3 = tf32_hi(a3);
                uint32_t al0 = tf32_hi(a0 - __uint_as_float(ah0));
                uint32_t al1 = tf32_hi(a1 - __uint_as_float(ah1));
                uint32_t al2 = tf32_hi(a2 - __uint_as_float(ah2));
                uint32_t al3 = tf32_hi(a3 - __uint_as_float(ah3));
#pragma unroll
                for (int j = 0; j < NT; ++j) {
                    const int brow = (lane >> 2) + 8 * j;
                    uint32_t bh0 = __float_as_uint(bH[brow * PITCH + kc]);
                    uint32_t bh1 = __float_as_uint(bH[brow * PITCH + kc + 4]);
                    uint32_t bl0 = __float_as_uint(bL[brow * PITCH + kc]);
                    uint32_t bl1 = __float_as_uint(bL[brow * PITCH + kc + 4]);
                    asm volatile(
                        "mma.sync.aligned.m16n8k8.row.col.f32.tf32.tf32.f32 "
                        "{%0,%1,%2,%3}, {%4,%5,%6,%7}, {%8,%9}, {%0,%1,%2,%3};"
                        : "+f"(acc[j][0]), "+f"(acc[j][1]), "+f"(acc[j][2]), "+f"(acc[j][3])
                        : "r"(ah0), "r"(ah1), "r"(ah2), "r"(ah3), "r"(bl0), "r"(bl1));
                    asm volatile(
                        "mma.sync.aligned.m16n8k8.row.col.f32.tf32.tf32.f32 "
                        "{%0,%1,%2,%3}, {%4,%5,%6,%7}, {%8,%9}, {%0,%1,%2,%3};"
                        : "+f"(acc[j][0]), "+f"(acc[j][1]), "+f"(acc[j][2]), "+f"(acc[j][3])
                        : "r"(al0), "r"(al1), "r"(al2), "r"(al3), "r"(bh0), "r"(bh1));
                    asm volatile(
                        "mma.sync.aligned.m16n8k8.row.col.f32.tf32.tf32.f32 "
                        "{%0,%1,%2,%3}, {%4,%5,%6,%7}, {%8,%9}, {%0,%1,%2,%3};"
                        : "+f"(acc[j][0]), "+f"(acc[j][1]), "+f"(acc[j][2]), "+f"(acc[j][3])
                        : "r"(ah0), "r"(ah1), "r"(ah2), "r"(ah3), "r"(bh0), "r"(bh1));
                }
            }
        }

        __syncthreads();   // all warps done reading stage t&1
        if (t + 2 < TILES) load_tile(t + 2, t & 1);
    }

    // epilogue: write split partials (8B stores)
    float* Pg = (NT == 5) ? g_Pp : g_Po;
    constexpr int NOUT = NR;
    const int r0 = row0 + wid * 16 + (lane >> 2);
    const int cb = (lane & 3) * 2;
    float* base = Pg + (size_t)blockIdx.y * N * NOUT;
#pragma unroll
    for (int j = 0; j < NT; ++j) {
        *reinterpret_cast<float2*>(base + (size_t)r0 * NOUT + j * 8 + cb) =
            make_float2(acc[j][0], acc[j][1]);
        *reinterpret_cast<float2*>(base + (size_t)(r0 + 8) * NOUT + j * 8 + cb) =
            make_float2(acc[j][2], acc[j][3]);
    }
}

// ============================ final reduce ==================================
__global__ void reduce_kernel(float* __restrict__ out)
{
    const int i = blockIdx.x * blockDim.x + threadIdx.x;  // < N*C
    float s = 0.f;
#pragma unroll
    for (int k = 0; k < KSPLIT; ++k) s += g_Po[(size_t)k * N * C + i];
    out[i] = s;
}

// ============================ launch ========================================
extern "C" void kernel_launch(void* const* d_in, const int* in_sizes, int n_in,
                              void* d_out, int out_size)
{
    const float* X  = (const float*)d_in[0];
    const float* A  = (const float*)d_in[1];
    const float* W1 = (const float*)d_in[2];
    const float* W2 = (const float*)d_in[3];
    const float* Wl = (const float*)d_in[4];
    const float* pk = (const float*)d_in[5];

    const int smem5 = STAGES * (ASTG + 2 * 40 * PITCH) * 4;   // 113152 B
    const int smem2 = STAGES * (ASTG + 2 * 16 * PITCH) * 4;   //  87040 B
    cudaFuncSetAttribute((const void*)gemm_mma<5>,
                         cudaFuncAttributeMaxDynamicSharedMemorySize, smem5);
    cudaFuncSetAttribute((const void*)gemm_mma<2>,
                         cudaFuncAttributeMaxDynamicSharedMemorySize, smem2);

    const dim3 ggrid(N / BM, KSPLIT);   // (64, 8)
    const int rgrid = N / 8;            // 1024 blocks, warp-per-row

    prep_kernel<<<rgrid, 256>>>(X, W1);
    gemm_mma<5><<<ggrid, 256, smem5>>>(A);
    post_prep_kernel<<<rgrid, 256>>>(W2);
    gemm_mma<5><<<ggrid, 256, smem5>>>(A);
    post_logits_kernel<<<rgrid, 256>>>(Wl, pk);
    gemm_mma<2><<<ggrid, 256, smem2>>>(A);
    reduce_kernel<<<(N * C) / 256, 256>>>((float*)d_out);
}

// round 16
// speedup vs baseline: 1.2524x; 1.2524x over previous
#include <cuda_runtime.h>
#include <cuda_bf16.h>
#include <cstdint>

#define FULLMASK 0xffffffffu

constexpr int N = 8192, D = 32, C = 16;
constexpr int NC1 = 40;                   // stored cols for layer GEMMs (34 real)
constexpr int KSPLIT = 16;
constexpr int BM = 256, BK = 64;
constexpr int TILES = (N / KSPLIT) / BK;  // 8
constexpr int PITCH = 72;                 // smem row pitch in bf16 (144 B)
constexpr int A_ELE = BM * PITCH;         // bf16 elems per A array per stage

// ---- scratch (static device arrays; zero-initialized, never allocated) ----
__device__ __align__(256) __nv_bfloat16 g_MtH[NC1 * N];     // M^T hi; rows 34..39 stay 0
__device__ __align__(256) __nv_bfloat16 g_MtL[NC1 * N];     // M^T lo
__device__ __align__(256) float g_Pp[KSPLIT * N * NC1];     // layer partials
__device__ __align__(256) float g_Po[KSPLIT * N * C];       // logits partials

__device__ __forceinline__ float wsum(float v) {
#pragma unroll
    for (int o = 16; o > 0; o >>= 1) v += __shfl_xor_sync(FULLMASK, v, o);
    return v;
}
__device__ __forceinline__ float artanh_c(float v) {
    v = fminf(fmaxf(v, -0.99999988f), 0.99999988f);
    return atanhf(v);
}

// ---- staged transposed hi/lo stores: [col][8 rows], flushed as 16B chunks --
__device__ __forceinline__ void stage_hl(__nv_bfloat16 (*tH)[8],
                                         __nv_bfloat16 (*tL)[8],
                                         int col, int w, float v)
{
    __nv_bfloat16 h = __float2bfloat16_rn(v);
    tH[col][w] = h;
    tL[col][w] = __float2bfloat16_rn(v - __bfloat162float(h));
}
template <int NCOLS>
__device__ __forceinline__ void store_cols_t(__nv_bfloat16 (*tH)[8],
                                             __nv_bfloat16 (*tL)[8],
                                             int tid, int row0)
{
    __syncthreads();
    if (tid < NCOLS) {
        *reinterpret_cast<uint4*>(&g_MtH[(size_t)tid * N + row0]) =
            *reinterpret_cast<const uint4*>(&tH[tid][0]);
        *reinterpret_cast<uint4*>(&g_MtL[(size_t)tid * N + row0]) =
            *reinterpret_cast<const uint4*>(&tL[tid][0]);
    }
}

// ---- prep math: x (lane=dim) -> stage gamma*XW | gamma-1 | 1 ---------------
__device__ __forceinline__ void prep_math(const float (*Ws)[D + 1], float x,
                                          int lane, int w,
                                          __nv_bfloat16 (*tH)[8],
                                          __nv_bfloat16 (*tL)[8])
{
    float xn = sqrtf(fmaxf(wsum(x * x), 1e-30f));
    float mx = 0.f;
#pragma unroll
    for (int d = 0; d < D; ++d)
        mx = fmaf(__shfl_sync(FULLMASK, x, d), Ws[d][lane], mx);
    float mxn = sqrtf(fmaxf(wsum(mx * mx), 1e-30f));
    float xw = tanhf(mxn / xn * artanh_c(xn)) / mxn * mx;
    float gamma = 2.f / fmaxf(1.f - wsum(xw * xw), 1e-15f);

    stage_hl(tH, tL, lane, w, gamma * xw);
    if (lane == 0) stage_hl(tH, tL, 32, w, gamma - 1.f);
    if (lane == 1) stage_hl(tH, tL, 33, w, 1.f);
}

// ---- post math: split partials -> layer output x (lane=dim) ----------------
__device__ __forceinline__ float post_math(int row, int lane)
{
    float nom = 0.f, den = 0.f, alp = 0.f;
#pragma unroll
    for (int s = 0; s < KSPLIT; ++s) {
        const float* pr = g_Pp + ((size_t)s * N + row) * NC1;
        nom += pr[lane]; den += pr[32]; alp += pr[33];
    }
    den = (den >= 0.f) ? fmaxf(den, 1e-10f) : fminf(den, -1e-10f);

    float v = nom / den;
    float vn = sqrtf(fmaxf(wsum(v * v), 1e-30f));
    float am = tanhf(0.5f * artanh_c(vn)) * (v / vn);
    float amn = sqrtf(fmaxf(wsum(am * am), 1e-30f));
    float axw = tanhf(alp * artanh_c(amn)) * (am / amn);
    float axwn = sqrtf(fmaxf(wsum(axw * axw), 1e-30f));
    float r = fmaxf(artanh_c(axwn) * (axw / axwn), 0.f);
    float rn = sqrtf(fmaxf(wsum(r * r), 1e-30f));
    return tanhf(rn) * (r / rn);
}

// ============================ layer-1 prep ==================================
__global__ void prep_kernel(const float* __restrict__ X0,
                            const float* __restrict__ W)
{
    __shared__ float Ws[D][D + 1];
    __shared__ __nv_bfloat16 tH[NC1][8], tL[NC1][8];
    const int tid = threadIdx.x;
    for (int i = tid; i < D * D; i += blockDim.x) Ws[i >> 5][i & 31] = W[i];
    __syncthreads();

    const int lane = tid & 31, w = tid >> 5;
    const int row0 = blockIdx.x * 8;
    prep_math(Ws, X0[(row0 + w) * D + lane], lane, w, tH, tL);
    store_cols_t<34>(tH, tL, tid, row0);
}

// ============================ fused post + prep (layer 2) ===================
__global__ void post_prep_kernel(const float* __restrict__ W)
{
    __shared__ float Ws[D][D + 1];
    __shared__ __nv_bfloat16 tH[NC1][8], tL[NC1][8];
    const int tid = threadIdx.x;
    for (int i = tid; i < D * D; i += blockDim.x) Ws[i >> 5][i & 31] = W[i];
    __syncthreads();

    const int lane = tid & 31, w = tid >> 5;
    const int row0 = blockIdx.x * 8;
    float x = post_math(row0 + w, lane);
    prep_math(Ws, x, lane, w, tH, tL);
    store_cols_t<34>(tH, tL, tid, row0);
}

// ============================ fused post + logits ===========================
__global__ void post_logits_kernel(const float* __restrict__ Wl,
                                   const float* __restrict__ pks)
{
    __shared__ float bs[C][D], ws[C][D];
    __shared__ float an_s[C], lam_s[C], b2_s[C];
    __shared__ __nv_bfloat16 tH[C][8], tL[C][8];
    const int tid = threadIdx.x;
    for (int i = tid; i < C * D; i += blockDim.x) {
        const int c = i >> 5, d = i & 31;
        bs[c][d] = pks[i];
        ws[c][d] = Wl[d * C + c];
    }
    __syncthreads();
    if (tid < C) {
        float s2 = 0.f, b2 = 0.f;
        for (int d = 0; d < D; ++d) { s2 += ws[tid][d] * ws[tid][d]; b2 += bs[tid][d] * bs[tid][d]; }
        an_s[tid] = fmaxf(sqrtf(s2), 1e-10f);
        b2_s[tid] = b2;
        lam_s[tid] = 2.f / fmaxf(1.f - b2, 1e-15f);
    }
    __syncthreads();

    const int lane = tid & 31, w = tid >> 5;
    const int row0 = blockIdx.x * 8;
    float x = post_math(row0 + w, lane);
    float y2 = wsum(x * x);

#pragma unroll 1
    for (int c = 0; c < C; ++c) {
        float bd = bs[c][lane];
        float bx = wsum(bd * x);
        float b2 = b2_s[c];
        float c1 = 1.f - 2.f * bx + y2;
        float c2 = 1.f - b2;
        float dd = fmaxf(1.f - 2.f * bx + b2 * y2, 1e-15f);
        float z = (c2 * x - c1 * bd) / dd;
        float za = wsum(z * ws[c][lane]);
        float zn = fmaxf(sqrtf(fmaxf(wsum(z * z), 1e-30f)), 1e-10f);
        float dist = asinhf(2.f * za / ((1.f - zn * zn) * an_s[c]));
        float lg = lam_s[c] * an_s[c] * dist;   // lane-uniform
        if (lane == 0) stage_hl(tH, tL, c, w, lg);
    }
    store_cols_t<C>(tH, tL, tid, row0);
}

// ============================ double-bf16 HMMA GEMM, BM=256 =================
// P[split][r][c] = sum over k in split of A[r,k] * Mt[c][k]
// hi/lo split both sides; product = hiA*hiB + hiA*loB + loA*hiB.
// 8 warps x 2 m16-fragments (rows wid*16 and wid*16+128) share B registers.
// Double-buffered dynamic smem; one __syncthreads per tile.
template <int NT>
__global__ void __launch_bounds__(256, 1) gemm_mma(const float* __restrict__ A)
{
    constexpr int NR = NT * 8;         // B rows (output cols)
    constexpr int BU = NR * 8;         // uint4 chunks per B array tile
    constexpr int B_ELE = NR * PITCH;  // bf16 elems per B array per stage

    extern __shared__ __nv_bfloat16 dyn[];
    __nv_bfloat16* AsH = dyn;                    // [2][A_ELE]
    __nv_bfloat16* AsL = dyn + 2 * A_ELE;
    __nv_bfloat16* BsH = dyn + 4 * A_ELE;        // [2][B_ELE]
    __nv_bfloat16* BsL = dyn + 4 * A_ELE + 2 * B_ELE;

    const int tid = threadIdx.x, wid = tid >> 5, lane = tid & 31;
    const int row0 = blockIdx.x * BM;
    const size_t kb0 = (size_t)blockIdx.y * (N / KSPLIT);

    // A global: thread covers rows (tid>>4)+16p (p=0..15), float4 chunk tid&15
    const float4* af4 = reinterpret_cast<const float4*>(
        A + ((size_t)(row0 + (tid >> 4)) * N + kb0)) + (tid & 15);
    const char* bbH = reinterpret_cast<const char*>(g_MtH + kb0);
    const char* bbL = reinterpret_cast<const char*>(g_MtL + kb0);
    const size_t bo0 = (size_t)(tid >> 3) * N * 2 + (tid & 7) * 16;
    const size_t bo1 = (size_t)((tid + 256) >> 3) * N * 2 + (tid & 7) * 16;

    const int asOff = (tid >> 4) * PITCH + (tid & 15) * 4;
    const int bsOff0 = (tid >> 3) * PITCH + (tid & 7) * 8;
    const int bsOff1 = ((tid + 256) >> 3) * PITCH + (tid & 7) * 8;

    float acc[2][NT][4];
#pragma unroll
    for (int f = 0; f < 2; ++f)
#pragma unroll
        for (int j = 0; j < NT; ++j)
#pragma unroll
            for (int q = 0; q < 4; ++q) acc[f][j][q] = 0.f;

    float4 ar[16];
    uint4 brH0, brH1, brL0, brL1;
#pragma unroll
    for (int p = 0; p < 16; ++p) ar[p] = af4[(size_t)p * 4 * N];
    if (BU >= 256 || tid < BU) {
        brH0 = *reinterpret_cast<const uint4*>(bbH + bo0);
        brL0 = *reinterpret_cast<const uint4*>(bbL + bo0);
    }
    if (BU > 256 && tid < BU - 256) {
        brH1 = *reinterpret_cast<const uint4*>(bbH + bo1);
        brL1 = *reinterpret_cast<const uint4*>(bbL + bo1);
    }

    for (int t = 0; t < TILES; ++t) {
        const int st = t & 1;
        __nv_bfloat16* aH = AsH + st * A_ELE;
        __nv_bfloat16* aL = AsL + st * A_ELE;
        __nv_bfloat16* bH = BsH + st * B_ELE;
        __nv_bfloat16* bL = BsL + st * B_ELE;

        // commit tile t: fp32 -> hi/lo bf16x2, 8B stores
#pragma unroll
        for (int p = 0; p < 16; ++p) {
            uint32_t h0, h1, l0, l1;
            asm("cvt.rn.bf16x2.f32 %0, %1, %2;" : "=r"(h0) : "f"(ar[p].y), "f"(ar[p].x));
            asm("cvt.rn.bf16x2.f32 %0, %1, %2;" : "=r"(h1) : "f"(ar[p].w), "f"(ar[p].z));
            float hx = __uint_as_float(h0 << 16);
            float hy = __uint_as_float(h0 & 0xFFFF0000u);
            float hz = __uint_as_float(h1 << 16);
            float hw = __uint_as_float(h1 & 0xFFFF0000u);
            asm("cvt.rn.bf16x2.f32 %0, %1, %2;" : "=r"(l0)
                : "f"(ar[p].y - hy), "f"(ar[p].x - hx));
            asm("cvt.rn.bf16x2.f32 %0, %1, %2;" : "=r"(l1)
                : "f"(ar[p].w - hw), "f"(ar[p].z - hz));
            *reinterpret_cast<uint2*>(&aH[asOff + p * 16 * PITCH]) = make_uint2(h0, h1);
            *reinterpret_cast<uint2*>(&aL[asOff + p * 16 * PITCH]) = make_uint2(l0, l1);
        }
        if (BU >= 256 || tid < BU) {
            *reinterpret_cast<uint4*>(&bH[bsOff0]) = brH0;
            *reinterpret_cast<uint4*>(&bL[bsOff0]) = brL0;
        }
        if (BU > 256 && tid < BU - 256) {
            *reinterpret_cast<uint4*>(&bH[bsOff1]) = brH1;
            *reinterpret_cast<uint4*>(&bL[bsOff1]) = brL1;
        }

        // prefetch tile t+1 into registers (no smem hazard)
        if (t + 1 < TILES) {
            const float4* ap = af4 + (size_t)(t + 1) * 16;
#pragma unroll
            for (int p = 0; p < 16; ++p) ar[p] = ap[(size_t)p * 4 * N];
            const size_t bshift = (size_t)(t + 1) * 128;
            if (BU >= 256 || tid < BU) {
                brH0 = *reinterpret_cast<const uint4*>(bbH + bshift + bo0);
                brL0 = *reinterpret_cast<const uint4*>(bbL + bshift + bo0);
            }
            if (BU > 256 && tid < BU - 256) {
                brH1 = *reinterpret_cast<const uint4*>(bbH + bshift + bo1);
                brL1 = *reinterpret_cast<const uint4*>(bbL + bshift + bo1);
            }
        }

        __syncthreads();   // tile t visible; prior-stage buffer freed safely

        // compute tile t: 4 k16-steps; per step: 2 A-frags, NT B-cols, 3 products
        const int kq2 = (lane & 3) * 2;
        const int boff = (lane >> 2) * PITCH + kq2;
#pragma unroll
        for (int s = 0; s < 4; ++s) {
            uint32_t ah[2][4], al[2][4];
#pragma unroll
            for (int f = 0; f < 2; ++f) {
                const int aoff = (wid * 16 + f * 128 + (lane >> 2)) * PITCH + kq2 + s * 16;
                ah[f][0] = *reinterpret_cast<const uint32_t*>(&aH[aoff]);
                ah[f][1] = *reinterpret_cast<const uint32_t*>(&aH[aoff + 8 * PITCH]);
                ah[f][2] = *reinterpret_cast<const uint32_t*>(&aH[aoff + 8]);
                ah[f][3] = *reinterpret_cast<const uint32_t*>(&aH[aoff + 8 * PITCH + 8]);
                al[f][0] = *reinterpret_cast<const uint32_t*>(&aL[aoff]);
                al[f][1] = *reinterpret_cast<const uint32_t*>(&aL[aoff + 8 * PITCH]);
                al[f][2] = *reinterpret_cast<const uint32_t*>(&aL[aoff + 8]);
                al[f][3] = *reinterpret_cast<const uint32_t*>(&aL[aoff + 8 * PITCH + 8]);
            }
#pragma unroll
            for (int j = 0; j < NT; ++j) {
                const int bo = boff + j * 8 * PITCH + s * 16;
                uint32_t bh0 = *reinterpret_cast<const uint32_t*>(&bH[bo]);
                uint32_t bh1 = *reinterpret_cast<const uint32_t*>(&bH[bo + 8]);
                uint32_t bl0 = *reinterpret_cast<const uint32_t*>(&bL[bo]);
                uint32_t bl1 = *reinterpret_cast<const uint32_t*>(&bL[bo + 8]);
#pragma unroll
                for (int f = 0; f < 2; ++f) {
                    asm volatile(
                        "mma.sync.aligned.m16n8k16.row.col.f32.bf16.bf16.f32 "
                        "{%0,%1,%2,%3}, {%4,%5,%6,%7}, {%8,%9}, {%0,%1,%2,%3};"
                        : "+f"(acc[f][j][0]), "+f"(acc[f][j][1]), "+f"(acc[f][j][2]), "+f"(acc[f][j][3])
                        : "r"(ah[f][0]), "r"(ah[f][1]), "r"(ah[f][2]), "r"(ah[f][3]),
                          "r"(bl0), "r"(bl1));
                    asm volatile(
                        "mma.sync.aligned.m16n8k16.row.col.f32.bf16.bf16.f32 "
                        "{%0,%1,%2,%3}, {%4,%5,%6,%7}, {%8,%9}, {%0,%1,%2,%3};"
                        : "+f"(acc[f][j][0]), "+f"(acc[f][j][1]), "+f"(acc[f][j][2]), "+f"(acc[f][j][3])
                        : "r"(al[f][0]), "r"(al[f][1]), "r"(al[f][2]), "r"(al[f][3]),
                          "r"(bh0), "r"(bh1));
                    asm volatile(
                        "mma.sync.aligned.m16n8k16.row.col.f32.bf16.bf16.f32 "
                        "{%0,%1,%2,%3}, {%4,%5,%6,%7}, {%8,%9}, {%0,%1,%2,%3};"
                        : "+f"(acc[f][j][0]), "+f"(acc[f][j][1]), "+f"(acc[f][j][2]), "+f"(acc[f][j][3])
                        : "r"(ah[f][0]), "r"(ah[f][1]), "r"(ah[f][2]), "r"(ah[f][3]),
                          "r"(bh0), "r"(bh1));
                }
            }
        }
    }

    // epilogue: write split partials (8B stores), both fragments
    float* Pg = (NT == 5) ? g_Pp : g_Po;
    constexpr int NOUT = NR;
    const int cb = (lane & 3) * 2;
    float* base = Pg + (size_t)blockIdx.y * N * NOUT;
#pragma unroll
    for (int f = 0; f < 2; ++f) {
        const int r0 = row0 + wid * 16 + f * 128 + (lane >> 2);
#pragma unroll
        for (int j = 0; j < NT; ++j) {
            *reinterpret_cast<float2*>(base + (size_t)r0 * NOUT + j * 8 + cb) =
                make_float2(acc[f][j][0], acc[f][j][1]);
            *reinterpret_cast<float2*>(base + (size_t)(r0 + 8) * NOUT + j * 8 + cb) =
                make_float2(acc[f][j][2], acc[f][j][3]);
        }
    }
}

// ============================ final reduce ==================================
__global__ void reduce_kernel(float* __restrict__ out)
{
    const int i = blockIdx.x * blockDim.x + threadIdx.x;  // < N*C
    float s = 0.f;
#pragma unroll
    for (int k = 0; k < KSPLIT; ++k) s += g_Po[(size_t)k * N * C + i];
    out[i] = s;
}

// ============================ launch ========================================
extern "C" void kernel_launch(void* const* d_in, const int* in_sizes, int n_in,
                              void* d_out, int out_size)
{
    const float* X  = (const float*)d_in[0];
    const float* A  = (const float*)d_in[1];
    const float* W1 = (const float*)d_in[2];
    const float* W2 = (const float*)d_in[3];
    const float* Wl = (const float*)d_in[4];
    const float* pk = (const float*)d_in[5];

    const int smem5 = (4 * A_ELE + 4 * 40 * PITCH) * 2;   // 170496 B
    const int smem2 = (4 * A_ELE + 4 * 16 * PITCH) * 2;   // 156672 B
    cudaFuncSetAttribute((const void*)gemm_mma<5>,
                         cudaFuncAttributeMaxDynamicSharedMemorySize, smem5);
    cudaFuncSetAttribute((const void*)gemm_mma<2>,
                         cudaFuncAttributeMaxDynamicSharedMemorySize, smem2);

    const dim3 ggrid(N / BM, KSPLIT);   // (32, 16)
    const int rgrid = N / 8;            // 1024 blocks, warp-per-row

    prep_kernel<<<rgrid, 256>>>(X, W1);
    gemm_mma<5><<<ggrid, 256, smem5>>>(A);
    post_prep_kernel<<<rgrid, 256>>>(W2);
    gemm_mma<5><<<ggrid, 256, smem5>>>(A);
    post_logits_kernel<<<rgrid, 256>>>(Wl, pk);
    gemm_mma<2><<<ggrid, 256, smem2>>>(A);
    reduce_kernel<<<(N * C) / 256, 256>>>((float*)d_out);
}